// round 3
// baseline (speedup 1.0000x reference)
#include <cuda_runtime.h>
#include <math.h>

#define MAX_NODE 200000
#define MAX_REL  401
#define DIM      64

// Scratch (no allocations allowed):
//   node table: [expmap0(h) (64) | A = h@Ws (64)] per node   (~102 MB)
//   rel  table: [expmap0(r) (64) | B = r@Wr (64) | C = r@Wqr+b (64)] per rel
//   agg buffer: scatter-sum destination (~51 MB)
__device__ float d_nodeT[(size_t)MAX_NODE * 128];
__device__ float d_relT[(size_t)MAX_REL * 192];
__device__ float d_agg[(size_t)MAX_NODE * 64];

// ---------------------------------------------------------------------------
// K1: relation table. One warp per relation. Lane l owns dims 2l, 2l+1.
// ---------------------------------------------------------------------------
__global__ void build_rel(const float* __restrict__ rela,
                          const float* __restrict__ Wr,
                          const float* __restrict__ Wqr,
                          const float* __restrict__ Wqr_b,
                          const float* __restrict__ curv, int nRel) {
    __shared__ float sh[8][64];
    int warp = threadIdx.x >> 5, lane = threadIdx.x & 31;
    int r = blockIdx.x * 8 + warp;
    if (r >= nRel) return;
    float c = fmaxf(curv[0], 1e-6f);
    float sc = sqrtf(c);

    float2 h = ((const float2*)(rela + (size_t)r * 64))[lane];
    sh[warp][2 * lane] = h.x;
    sh[warp][2 * lane + 1] = h.y;

    // expmap0 + project
    float n2 = h.x * h.x + h.y * h.y;
#pragma unroll
    for (int off = 16; off; off >>= 1) n2 += __shfl_xor_sync(~0u, n2, off);
    float un = fmaxf(sqrtf(n2), 1e-15f);
    float arg = fminf(sc * un, 15.0f);
    float t = tanhf(arg);
    float gs = t / (sc * un);
    float gn = fmaxf(un * gs, 1e-15f);
    float maxn = 0.996f / sc;
    if (gn > maxn) gs *= maxn / gn;

    float2* orow = (float2*)(d_relT + (size_t)r * 192);
    orow[lane] = make_float2(h.x * gs, h.y * gs);
    __syncwarp();

    // B = r @ Wr ; C = r @ Wqr + b
    float b0 = 0.f, b1 = 0.f;
    float c0 = Wqr_b[2 * lane], c1 = Wqr_b[2 * lane + 1];
    for (int i = 0; i < 64; i++) {
        float hi = sh[warp][i];
        float2 wr = ((const float2*)(Wr + (size_t)i * 64))[lane];
        float2 wq = ((const float2*)(Wqr + (size_t)i * 64))[lane];
        b0 = fmaf(hi, wr.x, b0); b1 = fmaf(hi, wr.y, b1);
        c0 = fmaf(hi, wq.x, c0); c1 = fmaf(hi, wq.y, c1);
    }
    orow[32 + lane] = make_float2(b0, b1);
    orow[64 + lane] = make_float2(c0, c1);
}

// ---------------------------------------------------------------------------
// K2: node table. Block = 64 threads handles 16 nodes. Thread t owns output
// column t of A = h@Ws (16-row register blocking: 16 FMAs per Ws load).
// Then the two warps compute expmap0 for 8 nodes each.
// ---------------------------------------------------------------------------
__global__ void build_node(const float* __restrict__ hidden,
                           const float* __restrict__ Ws,
                           const float* __restrict__ curv, int nNode) {
    __shared__ float sh[16][64];
    int t = threadIdx.x;  // 0..63
    int base = blockIdx.x * 16;
    float c = fmaxf(curv[0], 1e-6f);
    float sc = sqrtf(c);

#pragma unroll
    for (int k = 0; k < 16; k++) {
        int n = base + k;
        sh[k][t] = (n < nNode) ? hidden[(size_t)n * 64 + t] : 0.f;
    }
    __syncthreads();

    float acc[16];
#pragma unroll
    for (int k = 0; k < 16; k++) acc[k] = 0.f;

    for (int i = 0; i < 64; i += 4) {
        float w0 = Ws[(size_t)i * 64 + t];
        float w1 = Ws[(size_t)(i + 1) * 64 + t];
        float w2 = Ws[(size_t)(i + 2) * 64 + t];
        float w3 = Ws[(size_t)(i + 3) * 64 + t];
#pragma unroll
        for (int k = 0; k < 16; k++) {
            float4 hv = *(const float4*)&sh[k][i];
            acc[k] = fmaf(hv.x, w0, fmaf(hv.y, w1, fmaf(hv.z, w2, fmaf(hv.w, w3, acc[k]))));
        }
    }
#pragma unroll
    for (int k = 0; k < 16; k++) {
        int n = base + k;
        if (n < nNode) d_nodeT[(size_t)n * 128 + 64 + t] = acc[k];
    }

    // expmap0 per node; warp w handles nodes w, w+2, ...
    int warp = t >> 5, lane = t & 31;
    for (int k = warp; k < 16; k += 2) {
        int n = base + k;
        if (n >= nNode) continue;
        float h0 = sh[k][2 * lane], h1 = sh[k][2 * lane + 1];
        float n2 = h0 * h0 + h1 * h1;
#pragma unroll
        for (int off = 16; off; off >>= 1) n2 += __shfl_xor_sync(~0u, n2, off);
        float un = fmaxf(sqrtf(n2), 1e-15f);
        float arg = fminf(sc * un, 15.0f);
        float tt = tanhf(arg);
        float gs = tt / (sc * un);
        float gn = fmaxf(un * gs, 1e-15f);
        float maxn = 0.996f / sc;
        if (gn > maxn) gs *= maxn / gn;
        float2* orow = (float2*)(d_nodeT + (size_t)n * 128);
        orow[lane] = make_float2(h0 * gs, h1 * gs);
    }
}

// ---------------------------------------------------------------------------
// K3: zero the aggregation buffer.
// ---------------------------------------------------------------------------
__global__ void zero_agg(int nVec4) {
    int i = blockIdx.x * blockDim.x + threadIdx.x;
    if (i < nVec4) ((float4*)d_agg)[i] = make_float4(0.f, 0.f, 0.f, 0.f);
}

// ---------------------------------------------------------------------------
// K4: edge kernel. 2 edges per warp; each 16-lane half handles one edge,
// lane owns 4 consecutive dims (float4). Scatter via red.global.add.v4.f32
// (16 REDs per edge). No early return: full-mask shuffles stay defined.
// ---------------------------------------------------------------------------
__global__ void edge_kernel(const int* __restrict__ sub, const int* __restrict__ rel,
                            const int* __restrict__ obj, const int* __restrict__ qr,
                            const float* __restrict__ walpha_w,
                            const float* __restrict__ walpha_b,
                            const float* __restrict__ curv, int E) {
    int lane   = threadIdx.x & 31;
    int half   = lane >> 4;        // 0 or 1 within warp
    int l16    = lane & 15;        // lane within the 16-lane edge group
    int warpId = (blockIdx.x * blockDim.x + threadIdx.x) >> 5;
    long long e = (long long)warpId * 2 + half;
    bool valid = (e < E);
    int ei = valid ? (int)e : 0;

    float c = fmaxf(curv[0], 1e-6f);
    float sc = sqrtf(c);

    int s = __ldg(sub + ei);
    int r = __ldg(rel + ei);
    int o = __ldg(obj + ei);
    int q = __ldg(qr + ei);

    const float4* nrow = (const float4*)(d_nodeT + (size_t)s * 128);
    float4 x = nrow[l16];         // expmap0(hs) dims [4*l16..]
    float4 a = nrow[16 + l16];    // hs @ Ws
    const float4* rrow = (const float4*)(d_relT + (size_t)r * 192);
    float4 y = rrow[l16];         // expmap0(hr)
    float4 b = rrow[16 + l16];    // hr @ Wr
    const float4* qrow = (const float4*)(d_relT + (size_t)q * 192);
    float4 cq = qrow[32 + l16];   // h_qr @ Wqr + bias
    float4 w = ((const float4*)walpha_w)[l16];

    // partial dot products (4 dims per lane)
    float x2 = x.x * x.x + x.y * x.y + x.z * x.z + x.w * x.w;
    float y2 = y.x * y.x + y.y * y.y + y.z * y.z + y.w * y.w;
    float xy = x.x * y.x + x.y * y.y + x.z * y.z + x.w * y.w;
    float t0 = fmaxf(a.x + b.x + cq.x, 0.f);
    float t1 = fmaxf(a.y + b.y + cq.y, 0.f);
    float t2 = fmaxf(a.z + b.z + cq.z, 0.f);
    float t3 = fmaxf(a.w + b.w + cq.w, 0.f);
    float ap = t0 * w.x + t1 * w.y + t2 * w.z + t3 * w.w;
    // reduce within the 16-lane group (xor offsets <= 8 never cross groups)
#pragma unroll
    for (int off = 8; off; off >>= 1) {
        x2 += __shfl_xor_sync(~0u, x2, off);
        y2 += __shfl_xor_sync(~0u, y2, off);
        xy += __shfl_xor_sync(~0u, xy, off);
        ap += __shfl_xor_sync(~0u, ap, off);
    }

    // mobius_add
    float ca = 1.f + 2.f * c * xy + c * y2;
    float cb = 1.f - c * x2;
    float den = fmaxf(1.f + 2.f * c * xy + c * c * x2 * y2, 1e-15f);
    float inv_den = 1.f / den;
    float4 m;
    m.x = (ca * x.x + cb * y.x) * inv_den;
    m.y = (ca * x.y + cb * y.y) * inv_den;
    m.z = (ca * x.z + cb * y.z) * inv_den;
    m.w = (ca * x.w + cb * y.w) * inv_den;

    float m2 = m.x * m.x + m.y * m.y + m.z * m.z + m.w * m.w;
#pragma unroll
    for (int off = 8; off; off >>= 1) m2 += __shfl_xor_sync(~0u, m2, off);
    float mn = sqrtf(m2);

    // project + logmap0 folded into a scalar coefficient
    float maxn = 0.996f / sc;
    float pscale = 1.f, nrm = mn;
    if (mn > maxn) { pscale = maxn / mn; nrm = maxn; }
    float yn = fmaxf(nrm, 1e-15f);
    float u = fminf(sc * yn, 1.f - 1e-5f);
    float art = 0.5f * (log1pf(u) - log1pf(-u));
    float lf = art / (yn * sc);

    float alpha = 1.f / (1.f + expf(-(ap + walpha_b[0])));
    float coef = alpha * pscale * lf;

    if (valid) {
        float* dst = d_agg + (size_t)o * 64 + 4 * l16;  // 16B aligned
        float v0 = m.x * coef, v1 = m.y * coef, v2 = m.z * coef, v3 = m.w * coef;
        asm volatile("red.global.add.v4.f32 [%0], {%1, %2, %3, %4};"
                     :: "l"(dst), "f"(v0), "f"(v1), "f"(v2), "f"(v3) : "memory");
    }
}

// ---------------------------------------------------------------------------
// K5: out = agg @ Wh. Same register-blocked matvec as build_node.
// ---------------------------------------------------------------------------
__global__ void out_gemm(const float* __restrict__ Wh, float* __restrict__ out, int nNode) {
    __shared__ float sh[16][64];
    int t = threadIdx.x;
    int base = blockIdx.x * 16;
#pragma unroll
    for (int k = 0; k < 16; k++) {
        int n = base + k;
        sh[k][t] = (n < nNode) ? d_agg[(size_t)n * 64 + t] : 0.f;
    }
    __syncthreads();

    float acc[16];
#pragma unroll
    for (int k = 0; k < 16; k++) acc[k] = 0.f;

    for (int i = 0; i < 64; i += 4) {
        float w0 = Wh[(size_t)i * 64 + t];
        float w1 = Wh[(size_t)(i + 1) * 64 + t];
        float w2 = Wh[(size_t)(i + 2) * 64 + t];
        float w3 = Wh[(size_t)(i + 3) * 64 + t];
#pragma unroll
        for (int k = 0; k < 16; k++) {
            float4 hv = *(const float4*)&sh[k][i];
            acc[k] = fmaf(hv.x, w0, fmaf(hv.y, w1, fmaf(hv.z, w2, fmaf(hv.w, w3, acc[k]))));
        }
    }
#pragma unroll
    for (int k = 0; k < 16; k++) {
        int n = base + k;
        if (n < nNode) out[(size_t)n * 64 + t] = acc[k];
    }
}

// ---------------------------------------------------------------------------
extern "C" void kernel_launch(void* const* d_in, const int* in_sizes, int n_in,
                              void* d_out, int out_size) {
    const float* hidden   = (const float*)d_in[0];
    const float* rela     = (const float*)d_in[1];
    const float* Ws       = (const float*)d_in[2];
    const float* Wr       = (const float*)d_in[3];
    const float* Wqr      = (const float*)d_in[4];
    const float* Wqr_b    = (const float*)d_in[5];
    const float* walpha_w = (const float*)d_in[6];
    const float* walpha_b = (const float*)d_in[7];
    const float* Wh       = (const float*)d_in[8];
    const float* curv     = (const float*)d_in[9];
    const int* sub = (const int*)d_in[10];
    const int* rel = (const int*)d_in[11];
    const int* obj = (const int*)d_in[12];
    const int* qr  = (const int*)d_in[13];
    float* out = (float*)d_out;

    int nNode = in_sizes[0] / DIM;
    int nRel  = in_sizes[1] / DIM;
    int E     = in_sizes[10];

    build_rel<<<(nRel + 7) / 8, 256>>>(rela, Wr, Wqr, Wqr_b, curv, nRel);
    build_node<<<(nNode + 15) / 16, 64>>>(hidden, Ws, curv, nNode);
    zero_agg<<<(nNode * 16 + 255) / 256, 256>>>(nNode * 16);
    // 2 edges per warp -> E/2 warps
    int warpsNeeded = (E + 1) / 2;
    int blocks = (warpsNeeded + 7) / 8;  // 8 warps per 256-thread block
    edge_kernel<<<blocks, 256>>>(sub, rel, obj, qr, walpha_w, walpha_b, curv, E);
    out_gemm<<<(nNode + 15) / 16, 64>>>(Wh, out, nNode);
}

// round 4
// speedup vs baseline: 1.3282x; 1.3282x over previous
#include <cuda_runtime.h>
#include <math.h>

#define MAX_NODE 200000
#define MAX_REL  401
#define DIM      64

// Scratch:
//   node table: [expmap0(h) (64) | A = h@Ws (64)] per node   (~102 MB)
//   rel  table: [expmap0(r) (64) | B = r@Wr (64) | C = r@Wqr+b (64)] per rel
//   agg buffer: scatter-sum destination (~51 MB)
__device__ float d_nodeT[(size_t)MAX_NODE * 128];
__device__ float d_relT[(size_t)MAX_REL * 192];
__device__ float d_agg[(size_t)MAX_NODE * 64];

// ---- packed fp32x2 helpers (Blackwell) ------------------------------------
__device__ __forceinline__ unsigned long long pk2(float a, float b) {
    unsigned long long r;
    asm("mov.b64 %0, {%1, %2};" : "=l"(r) : "f"(a), "f"(b));
    return r;
}
__device__ __forceinline__ unsigned long long fma2(unsigned long long a,
                                                   unsigned long long b,
                                                   unsigned long long c) {
    unsigned long long d;
    asm("fma.rn.f32x2 %0, %1, %2, %3;" : "=l"(d) : "l"(a), "l"(b), "l"(c));
    return d;
}
__device__ __forceinline__ void upk2(unsigned long long v, float& lo, float& hi) {
    asm("mov.b64 {%0, %1}, %2;" : "=f"(lo), "=f"(hi) : "l"(v));
}

// ---------------------------------------------------------------------------
// K1: relation table. One warp per relation. Lane l owns dims 2l, 2l+1.
// ---------------------------------------------------------------------------
__global__ void build_rel(const float* __restrict__ rela,
                          const float* __restrict__ Wr,
                          const float* __restrict__ Wqr,
                          const float* __restrict__ Wqr_b,
                          const float* __restrict__ curv, int nRel) {
    __shared__ float sh[8][64];
    int warp = threadIdx.x >> 5, lane = threadIdx.x & 31;
    int r = blockIdx.x * 8 + warp;
    if (r >= nRel) return;
    float c = fmaxf(curv[0], 1e-6f);
    float sc = sqrtf(c);

    float2 h = ((const float2*)(rela + (size_t)r * 64))[lane];
    sh[warp][2 * lane] = h.x;
    sh[warp][2 * lane + 1] = h.y;

    float n2 = h.x * h.x + h.y * h.y;
#pragma unroll
    for (int off = 16; off; off >>= 1) n2 += __shfl_xor_sync(~0u, n2, off);
    float un = fmaxf(sqrtf(n2), 1e-15f);
    float arg = fminf(sc * un, 15.0f);
    float t = tanhf(arg);
    float gs = t / (sc * un);
    float gn = fmaxf(un * gs, 1e-15f);
    float maxn = 0.996f / sc;
    if (gn > maxn) gs *= maxn / gn;

    float2* orow = (float2*)(d_relT + (size_t)r * 192);
    orow[lane] = make_float2(h.x * gs, h.y * gs);
    __syncwarp();

    float b0 = 0.f, b1 = 0.f;
    float c0 = Wqr_b[2 * lane], c1 = Wqr_b[2 * lane + 1];
    for (int i = 0; i < 64; i++) {
        float hi = sh[warp][i];
        float2 wr = ((const float2*)(Wr + (size_t)i * 64))[lane];
        float2 wq = ((const float2*)(Wqr + (size_t)i * 64))[lane];
        b0 = fmaf(hi, wr.x, b0); b1 = fmaf(hi, wr.y, b1);
        c0 = fmaf(hi, wq.x, c0); c1 = fmaf(hi, wq.y, c1);
    }
    orow[32 + lane] = make_float2(b0, b1);
    orow[64 + lane] = make_float2(c0, c1);
}

// ---------------------------------------------------------------------------
// K2: node table. Block = 64 threads, 16 nodes. Matvec A = h@Ws with 4-node x
// 4-col register tiles using packed f32x2 FMA; thread t: colgroup = (t&15)*4,
// nodegroup = t>>4 (nodes ng*4..ng*4+3). Then expmap0 per node (warp code).
// ---------------------------------------------------------------------------
__global__ void build_node(const float* __restrict__ hidden,
                           const float* __restrict__ Ws,
                           const float* __restrict__ curv, int nNode) {
    __shared__ float sh[16][64];
    int t = threadIdx.x;  // 0..63
    int base = blockIdx.x * 16;
    float c = fmaxf(curv[0], 1e-6f);
    float sc = sqrtf(c);

#pragma unroll
    for (int k = 0; k < 16; k++) {
        int n = base + k;
        sh[k][t] = (n < nNode) ? hidden[(size_t)n * 64 + t] : 0.f;
    }
    __syncthreads();

    int c4 = (t & 15) * 4;   // output column base
    int ng = (t >> 4) * 4;   // node base within tile

    unsigned long long accA[4], accB[4];
#pragma unroll
    for (int j = 0; j < 4; j++) { accA[j] = pk2(0.f, 0.f); accB[j] = pk2(0.f, 0.f); }

    for (int ib = 0; ib < 64; ib += 4) {
        float4 w0 = *(const float4*)&Ws[(size_t)(ib + 0) * 64 + c4];
        float4 w1 = *(const float4*)&Ws[(size_t)(ib + 1) * 64 + c4];
        float4 w2 = *(const float4*)&Ws[(size_t)(ib + 2) * 64 + c4];
        float4 w3 = *(const float4*)&Ws[(size_t)(ib + 3) * 64 + c4];
        unsigned long long wA0 = pk2(w0.x, w0.y), wB0 = pk2(w0.z, w0.w);
        unsigned long long wA1 = pk2(w1.x, w1.y), wB1 = pk2(w1.z, w1.w);
        unsigned long long wA2 = pk2(w2.x, w2.y), wB2 = pk2(w2.z, w2.w);
        unsigned long long wA3 = pk2(w3.x, w3.y), wB3 = pk2(w3.z, w3.w);
#pragma unroll
        for (int j = 0; j < 4; j++) {
            float4 hv = *(const float4*)&sh[ng + j][ib];
            unsigned long long h0 = pk2(hv.x, hv.x);
            unsigned long long h1 = pk2(hv.y, hv.y);
            unsigned long long h2 = pk2(hv.z, hv.z);
            unsigned long long h3 = pk2(hv.w, hv.w);
            accA[j] = fma2(h0, wA0, accA[j]); accB[j] = fma2(h0, wB0, accB[j]);
            accA[j] = fma2(h1, wA1, accA[j]); accB[j] = fma2(h1, wB1, accB[j]);
            accA[j] = fma2(h2, wA2, accA[j]); accB[j] = fma2(h2, wB2, accB[j]);
            accA[j] = fma2(h3, wA3, accA[j]); accB[j] = fma2(h3, wB3, accB[j]);
        }
    }
#pragma unroll
    for (int j = 0; j < 4; j++) {
        int n = base + ng + j;
        if (n < nNode) {
            float4 o;
            upk2(accA[j], o.x, o.y);
            upk2(accB[j], o.z, o.w);
            *(float4*)&d_nodeT[(size_t)n * 128 + 64 + c4] = o;
        }
    }

    // expmap0 per node; warp w handles nodes w, w+2, ...
    int warp = t >> 5, lane = t & 31;
    for (int k = warp; k < 16; k += 2) {
        int n = base + k;
        if (n >= nNode) continue;
        float h0 = sh[k][2 * lane], h1 = sh[k][2 * lane + 1];
        float n2 = h0 * h0 + h1 * h1;
#pragma unroll
        for (int off = 16; off; off >>= 1) n2 += __shfl_xor_sync(~0u, n2, off);
        float un = fmaxf(sqrtf(n2), 1e-15f);
        float arg = fminf(sc * un, 15.0f);
        float tt = tanhf(arg);
        float gs = tt / (sc * un);
        float gn = fmaxf(un * gs, 1e-15f);
        float maxn = 0.996f / sc;
        if (gn > maxn) gs *= maxn / gn;
        float2* orow = (float2*)(d_nodeT + (size_t)n * 128);
        orow[lane] = make_float2(h0 * gs, h1 * gs);
    }
}

// ---------------------------------------------------------------------------
// K3: zero the aggregation buffer.
// ---------------------------------------------------------------------------
__global__ void zero_agg(int nVec4) {
    int i = blockIdx.x * blockDim.x + threadIdx.x;
    if (i < nVec4) ((float4*)d_agg)[i] = make_float4(0.f, 0.f, 0.f, 0.f);
}

// ---------------------------------------------------------------------------
// K4: edge kernel. 4 edges per warp; 8 lanes per edge; lane owns dims
// [4*l8,4*l8+4) and [32+4*l8,32+4*l8+4) (two float4s, fully coalesced per
// group). Single shuffle-reduction set; |m|^2 computed algebraically from
// reduced scalars (no second reduction). Scatter: 2x red.global.add.v4.f32.
// ---------------------------------------------------------------------------
__global__ void edge_kernel(const int* __restrict__ sub, const int* __restrict__ rel,
                            const int* __restrict__ obj, const int* __restrict__ qr,
                            const float* __restrict__ walpha_w,
                            const float* __restrict__ walpha_b,
                            const float* __restrict__ curv, int E) {
    int lane = threadIdx.x & 31;
    int g    = lane >> 3;   // edge group 0..3 within warp
    int l8   = lane & 7;    // lane within 8-lane edge group
    int warpId = (blockIdx.x * blockDim.x + threadIdx.x) >> 5;
    long long e = (long long)warpId * 4 + g;
    bool valid = (e < E);
    int ei = valid ? (int)e : 0;

    float c = fmaxf(__ldg(curv), 1e-6f);
    float sc = sqrtf(c);

    int s = __ldg(sub + ei);
    int r = __ldg(rel + ei);
    int o = __ldg(obj + ei);
    int q = __ldg(qr + ei);

    const float4* nrow = (const float4*)(d_nodeT + (size_t)s * 128);
    const float4* rrow = (const float4*)(d_relT + (size_t)r * 192);
    const float4* qrow = (const float4*)(d_relT + (size_t)q * 192);
    const float4* w4   = (const float4*)walpha_w;

    float4 x0 = nrow[l8],      x1 = nrow[8 + l8];       // expmap0(hs)
    float4 a0 = nrow[16 + l8], a1 = nrow[24 + l8];      // hs @ Ws
    float4 y0 = rrow[l8],      y1 = rrow[8 + l8];       // expmap0(hr)
    float4 b0 = rrow[16 + l8], b1 = rrow[24 + l8];      // hr @ Wr
    float4 c0 = qrow[32 + l8], c1 = qrow[40 + l8];      // h_qr @ Wqr + bias
    float4 w0 = w4[l8],        w1 = w4[8 + l8];

    // partial dot products (8 dims per lane)
    float x2 = x0.x*x0.x + x0.y*x0.y + x0.z*x0.z + x0.w*x0.w
             + x1.x*x1.x + x1.y*x1.y + x1.z*x1.z + x1.w*x1.w;
    float y2 = y0.x*y0.x + y0.y*y0.y + y0.z*y0.z + y0.w*y0.w
             + y1.x*y1.x + y1.y*y1.y + y1.z*y1.z + y1.w*y1.w;
    float xy = x0.x*y0.x + x0.y*y0.y + x0.z*y0.z + x0.w*y0.w
             + x1.x*y1.x + x1.y*y1.y + x1.z*y1.z + x1.w*y1.w;
    float ap = fmaxf(a0.x + b0.x + c0.x, 0.f) * w0.x
             + fmaxf(a0.y + b0.y + c0.y, 0.f) * w0.y
             + fmaxf(a0.z + b0.z + c0.z, 0.f) * w0.z
             + fmaxf(a0.w + b0.w + c0.w, 0.f) * w0.w
             + fmaxf(a1.x + b1.x + c1.x, 0.f) * w1.x
             + fmaxf(a1.y + b1.y + c1.y, 0.f) * w1.y
             + fmaxf(a1.z + b1.z + c1.z, 0.f) * w1.z
             + fmaxf(a1.w + b1.w + c1.w, 0.f) * w1.w;

    // reduce within the 8-lane group (xor offsets <= 4 stay inside the group)
#pragma unroll
    for (int off = 4; off; off >>= 1) {
        x2 += __shfl_xor_sync(~0u, x2, off);
        y2 += __shfl_xor_sync(~0u, y2, off);
        xy += __shfl_xor_sync(~0u, xy, off);
        ap += __shfl_xor_sync(~0u, ap, off);
    }

    // mobius_add coefficients; |m|^2 from reduced scalars (no 2nd reduction)
    float ca = 1.f + 2.f * c * xy + c * y2;
    float cb = 1.f - c * x2;
    float den = fmaxf(1.f + 2.f * c * xy + c * c * x2 * y2, 1e-15f);
    float inv_den = 1.f / den;
    float m2 = ca * ca * x2 + 2.f * ca * cb * xy + cb * cb * y2;
    float mn = sqrtf(m2) * inv_den;

    // project + logmap0 folded into one scalar coefficient
    float maxn = 0.996f / sc;
    float pscale = 1.f, nrm = mn;
    if (mn > maxn) { pscale = maxn / mn; nrm = maxn; }
    float yn = fmaxf(nrm, 1e-15f);
    float u = fminf(sc * yn, 1.f - 1e-5f);
    float art = 0.5f * (log1pf(u) - log1pf(-u));
    float lf = art / (yn * sc);

    float alpha = 1.f / (1.f + expf(-(ap + __ldg(walpha_b))));
    float coef = alpha * pscale * lf * inv_den;
    float va = ca * coef, vb = cb * coef;

    if (valid) {
        float* dst = d_agg + (size_t)o * 64 + 4 * l8;
        float p0 = va * x0.x + vb * y0.x;
        float p1 = va * x0.y + vb * y0.y;
        float p2 = va * x0.z + vb * y0.z;
        float p3 = va * x0.w + vb * y0.w;
        asm volatile("red.global.add.v4.f32 [%0], {%1, %2, %3, %4};"
                     :: "l"(dst), "f"(p0), "f"(p1), "f"(p2), "f"(p3) : "memory");
        float q0 = va * x1.x + vb * y1.x;
        float q1 = va * x1.y + vb * y1.y;
        float q2 = va * x1.z + vb * y1.z;
        float q3 = va * x1.w + vb * y1.w;
        asm volatile("red.global.add.v4.f32 [%0], {%1, %2, %3, %4};"
                     :: "l"(dst + 32), "f"(q0), "f"(q1), "f"(q2), "f"(q3) : "memory");
    }
}

// ---------------------------------------------------------------------------
// K5: out = agg @ Wh. Same f32x2 register-tiled matvec as build_node.
// ---------------------------------------------------------------------------
__global__ void out_gemm(const float* __restrict__ Wh, float* __restrict__ out, int nNode) {
    __shared__ float sh[16][64];
    int t = threadIdx.x;
    int base = blockIdx.x * 16;
#pragma unroll
    for (int k = 0; k < 16; k++) {
        int n = base + k;
        sh[k][t] = (n < nNode) ? d_agg[(size_t)n * 64 + t] : 0.f;
    }
    __syncthreads();

    int c4 = (t & 15) * 4;
    int ng = (t >> 4) * 4;

    unsigned long long accA[4], accB[4];
#pragma unroll
    for (int j = 0; j < 4; j++) { accA[j] = pk2(0.f, 0.f); accB[j] = pk2(0.f, 0.f); }

    for (int ib = 0; ib < 64; ib += 4) {
        float4 w0 = *(const float4*)&Wh[(size_t)(ib + 0) * 64 + c4];
        float4 w1 = *(const float4*)&Wh[(size_t)(ib + 1) * 64 + c4];
        float4 w2 = *(const float4*)&Wh[(size_t)(ib + 2) * 64 + c4];
        float4 w3 = *(const float4*)&Wh[(size_t)(ib + 3) * 64 + c4];
        unsigned long long wA0 = pk2(w0.x, w0.y), wB0 = pk2(w0.z, w0.w);
        unsigned long long wA1 = pk2(w1.x, w1.y), wB1 = pk2(w1.z, w1.w);
        unsigned long long wA2 = pk2(w2.x, w2.y), wB2 = pk2(w2.z, w2.w);
        unsigned long long wA3 = pk2(w3.x, w3.y), wB3 = pk2(w3.z, w3.w);
#pragma unroll
        for (int j = 0; j < 4; j++) {
            float4 hv = *(const float4*)&sh[ng + j][ib];
            unsigned long long h0 = pk2(hv.x, hv.x);
            unsigned long long h1 = pk2(hv.y, hv.y);
            unsigned long long h2 = pk2(hv.z, hv.z);
            unsigned long long h3 = pk2(hv.w, hv.w);
            accA[j] = fma2(h0, wA0, accA[j]); accB[j] = fma2(h0, wB0, accB[j]);
            accA[j] = fma2(h1, wA1, accA[j]); accB[j] = fma2(h1, wB1, accB[j]);
            accA[j] = fma2(h2, wA2, accA[j]); accB[j] = fma2(h2, wB2, accB[j]);
            accA[j] = fma2(h3, wA3, accA[j]); accB[j] = fma2(h3, wB3, accB[j]);
        }
    }
#pragma unroll
    for (int j = 0; j < 4; j++) {
        int n = base + ng + j;
        if (n < nNode) {
            float4 o;
            upk2(accA[j], o.x, o.y);
            upk2(accB[j], o.z, o.w);
            *(float4*)&out[(size_t)n * 64 + c4] = o;
        }
    }
}

// ---------------------------------------------------------------------------
extern "C" void kernel_launch(void* const* d_in, const int* in_sizes, int n_in,
                              void* d_out, int out_size) {
    const float* hidden   = (const float*)d_in[0];
    const float* rela     = (const float*)d_in[1];
    const float* Ws       = (const float*)d_in[2];
    const float* Wr       = (const float*)d_in[3];
    const float* Wqr      = (const float*)d_in[4];
    const float* Wqr_b    = (const float*)d_in[5];
    const float* walpha_w = (const float*)d_in[6];
    const float* walpha_b = (const float*)d_in[7];
    const float* Wh       = (const float*)d_in[8];
    const float* curv     = (const float*)d_in[9];
    const int* sub = (const int*)d_in[10];
    const int* rel = (const int*)d_in[11];
    const int* obj = (const int*)d_in[12];
    const int* qr  = (const int*)d_in[13];
    float* out = (float*)d_out;

    int nNode = in_sizes[0] / DIM;
    int nRel  = in_sizes[1] / DIM;
    int E     = in_sizes[10];

    zero_agg<<<(nNode * 16 + 255) / 256, 256>>>(nNode * 16);
    build_rel<<<(nRel + 7) / 8, 256>>>(rela, Wr, Wqr, Wqr_b, curv, nRel);
    build_node<<<(nNode + 15) / 16, 64>>>(hidden, Ws, curv, nNode);
    // 4 edges per warp, 8 warps per 256-thread block -> 32 edges per block
    int blocks = (E + 31) / 32;
    edge_kernel<<<blocks, 256>>>(sub, rel, obj, qr, walpha_w, walpha_b, curv, E);
    out_gemm<<<(nNode + 15) / 16, 64>>>(Wh, out, nNode);
}

// round 6
// speedup vs baseline: 1.3936x; 1.0492x over previous
#include <cuda_runtime.h>
#include <cuda_fp16.h>
#include <math.h>

#define MAX_NODE 200000
#define MAX_REL  401
#define DIM      64
#define NODE_STRIDE 96   // floats per node row: 64 fp32 x | 64 fp16 A (=32 float slots)

// Scratch:
//   node table: [expmap0(h): 64 fp32 | A=h@Ws: 64 fp16 PERMUTED] per node (~77 MB)
//     A permutation: uint4 slot p (bytes 256+16p) = columns {4p..4p+3, 32+4p..32+4p+3}
//   rel  table: [expmap0(r) 64 | B=r@Wr 64 | C=r@Wqr+b 64] fp32 per rel (~300 KB)
//   agg buffer: scatter-sum destination (~51 MB)
__device__ float d_nodeT[(size_t)MAX_NODE * NODE_STRIDE];
__device__ float d_relT[(size_t)MAX_REL * 192];
__device__ float d_agg[(size_t)MAX_NODE * 64];

// ---- packed fp32x2 helpers (Blackwell f32x2 pipe) -------------------------
__device__ __forceinline__ unsigned long long pk2(float a, float b) {
    unsigned long long r;
    asm("mov.b64 %0, {%1, %2};" : "=l"(r) : "f"(a), "f"(b));
    return r;
}
__device__ __forceinline__ unsigned long long fma2(unsigned long long a,
                                                   unsigned long long b,
                                                   unsigned long long c) {
    unsigned long long d;
    asm("fma.rn.f32x2 %0, %1, %2, %3;" : "=l"(d) : "l"(a), "l"(b), "l"(c));
    return d;
}
__device__ __forceinline__ void upk2(unsigned long long v, float& lo, float& hi) {
    asm("mov.b64 {%0, %1}, %2;" : "=f"(lo), "=f"(hi) : "l"(v));
}

// ---------------------------------------------------------------------------
// K1: relation table. One warp per relation. Lane l owns dims 2l, 2l+1.
// ---------------------------------------------------------------------------
__global__ void build_rel(const float* __restrict__ rela,
                          const float* __restrict__ Wr,
                          const float* __restrict__ Wqr,
                          const float* __restrict__ Wqr_b,
                          const float* __restrict__ curv, int nRel) {
    __shared__ float sh[8][64];
    int warp = threadIdx.x >> 5, lane = threadIdx.x & 31;
    int r = blockIdx.x * 8 + warp;
    if (r >= nRel) return;
    float c = fmaxf(curv[0], 1e-6f);
    float sc = sqrtf(c);

    float2 h = ((const float2*)(rela + (size_t)r * 64))[lane];
    sh[warp][2 * lane] = h.x;
    sh[warp][2 * lane + 1] = h.y;

    float n2 = h.x * h.x + h.y * h.y;
#pragma unroll
    for (int off = 16; off; off >>= 1) n2 += __shfl_xor_sync(~0u, n2, off);
    float un = fmaxf(sqrtf(n2), 1e-15f);
    float arg = fminf(sc * un, 15.0f);
    float t = tanhf(arg);
    float gs = t / (sc * un);
    float gn = fmaxf(un * gs, 1e-15f);
    float maxn = 0.996f / sc;
    if (gn > maxn) gs *= maxn / gn;

    float2* orow = (float2*)(d_relT + (size_t)r * 192);
    orow[lane] = make_float2(h.x * gs, h.y * gs);
    __syncwarp();

    float b0 = 0.f, b1 = 0.f;
    float c0 = Wqr_b[2 * lane], c1 = Wqr_b[2 * lane + 1];
    for (int i = 0; i < 64; i++) {
        float hi = sh[warp][i];
        float2 wr = ((const float2*)(Wr + (size_t)i * 64))[lane];
        float2 wq = ((const float2*)(Wqr + (size_t)i * 64))[lane];
        b0 = fmaf(hi, wr.x, b0); b1 = fmaf(hi, wr.y, b1);
        c0 = fmaf(hi, wq.x, c0); c1 = fmaf(hi, wq.y, c1);
    }
    orow[32 + lane] = make_float2(b0, b1);
    orow[64 + lane] = make_float2(c0, c1);
}

// ---------------------------------------------------------------------------
// K2: node table + agg zeroing. Block = 64 threads, 16 nodes.
// A = h@Ws via 4-node x 4-col f32x2 register tiles; A stored as fp16 in the
// PERMUTED layout (see header comment). Agg rows zeroed here.
// ---------------------------------------------------------------------------
__global__ void build_node(const float* __restrict__ hidden,
                           const float* __restrict__ Ws,
                           const float* __restrict__ curv, int nNode) {
    __shared__ float sh[16][64];
    int t = threadIdx.x;  // 0..63
    int base = blockIdx.x * 16;
    float c = fmaxf(curv[0], 1e-6f);
    float sc = sqrtf(c);

    // zero agg rows for these 16 nodes (256 float4s, 4 per thread)
    float4 z = make_float4(0.f, 0.f, 0.f, 0.f);
#pragma unroll
    for (int i = t; i < 256; i += 64) {
        int n = base + (i >> 4);
        if (n < nNode) ((float4*)(d_agg + (size_t)n * 64))[i & 15] = z;
    }

#pragma unroll
    for (int k = 0; k < 16; k++) {
        int n = base + k;
        sh[k][t] = (n < nNode) ? hidden[(size_t)n * 64 + t] : 0.f;
    }
    __syncthreads();

    int c4 = (t & 15) * 4;   // output column base (0,4,...,60)
    int ng = (t >> 4) * 4;   // node base within tile

    unsigned long long accA[4], accB[4];
#pragma unroll
    for (int j = 0; j < 4; j++) { accA[j] = pk2(0.f, 0.f); accB[j] = pk2(0.f, 0.f); }

    for (int ib = 0; ib < 64; ib += 4) {
        float4 w0 = *(const float4*)&Ws[(size_t)(ib + 0) * 64 + c4];
        float4 w1 = *(const float4*)&Ws[(size_t)(ib + 1) * 64 + c4];
        float4 w2 = *(const float4*)&Ws[(size_t)(ib + 2) * 64 + c4];
        float4 w3 = *(const float4*)&Ws[(size_t)(ib + 3) * 64 + c4];
        unsigned long long wA0 = pk2(w0.x, w0.y), wB0 = pk2(w0.z, w0.w);
        unsigned long long wA1 = pk2(w1.x, w1.y), wB1 = pk2(w1.z, w1.w);
        unsigned long long wA2 = pk2(w2.x, w2.y), wB2 = pk2(w2.z, w2.w);
        unsigned long long wA3 = pk2(w3.x, w3.y), wB3 = pk2(w3.z, w3.w);
#pragma unroll
        for (int j = 0; j < 4; j++) {
            float4 hv = *(const float4*)&sh[ng + j][ib];
            unsigned long long h0 = pk2(hv.x, hv.x);
            unsigned long long h1 = pk2(hv.y, hv.y);
            unsigned long long h2 = pk2(hv.z, hv.z);
            unsigned long long h3 = pk2(hv.w, hv.w);
            accA[j] = fma2(h0, wA0, accA[j]); accB[j] = fma2(h0, wB0, accB[j]);
            accA[j] = fma2(h1, wA1, accA[j]); accB[j] = fma2(h1, wB1, accB[j]);
            accA[j] = fma2(h2, wA2, accA[j]); accB[j] = fma2(h2, wB2, accB[j]);
            accA[j] = fma2(h3, wA3, accA[j]); accB[j] = fma2(h3, wB3, accB[j]);
        }
    }
    // Permuted fp16 store: columns c4..c4+3 go to
    //   c4 < 32 : bytes 256 + 16*(c4/4)      (first half of uint4 slot c4/4)
    //   c4 >= 32: bytes 256 + 16*((c4-32)/4) + 8  (second half of that slot)
    int a_off = (c4 < 32) ? (256 + 4 * c4) : (256 + 4 * (c4 - 32) + 8);
#pragma unroll
    for (int j = 0; j < 4; j++) {
        int n = base + ng + j;
        if (n < nNode) {
            float a0, a1, a2, a3;
            upk2(accA[j], a0, a1);
            upk2(accB[j], a2, a3);
            __half2 h01 = __floats2half2_rn(a0, a1);
            __half2 h23 = __floats2half2_rn(a2, a3);
            uint2 st;
            st.x = *(unsigned*)&h01;
            st.y = *(unsigned*)&h23;
            *(uint2*)((char*)(d_nodeT + (size_t)n * NODE_STRIDE) + a_off) = st;
        }
    }

    // expmap0 per node; warp w handles nodes w, w+2, ...
    int warp = t >> 5, lane = t & 31;
    for (int k = warp; k < 16; k += 2) {
        int n = base + k;
        if (n >= nNode) continue;
        float h0 = sh[k][2 * lane], h1 = sh[k][2 * lane + 1];
        float n2 = h0 * h0 + h1 * h1;
#pragma unroll
        for (int off = 16; off; off >>= 1) n2 += __shfl_xor_sync(~0u, n2, off);
        float un = fmaxf(sqrtf(n2), 1e-15f);
        float arg = fminf(sc * un, 15.0f);
        float tt = tanhf(arg);
        float gs = tt / (sc * un);
        float gn = fmaxf(un * gs, 1e-15f);
        float maxn = 0.996f / sc;
        if (gn > maxn) gs *= maxn / gn;
        float2* orow = (float2*)(d_nodeT + (size_t)n * NODE_STRIDE);
        orow[lane] = make_float2(h0 * gs, h1 * gs);
    }
}

// ---------------------------------------------------------------------------
// K3: edge kernel. 4 edges per warp; 8 lanes per edge; lane owns the split
// dim set {4*l8.., 32+4*l8..}. Node gather: 2x float4 (x) + 1x uint4 (A fp16,
// permuted layout matches the split set exactly). Scatter: 2x red.v4.f32.
// ---------------------------------------------------------------------------
__global__ void __launch_bounds__(256)
edge_kernel(const int* __restrict__ sub, const int* __restrict__ rel,
            const int* __restrict__ obj, const int* __restrict__ qr,
            const float* __restrict__ walpha_w,
            const float* __restrict__ walpha_b,
            const float* __restrict__ curv, int E) {
    int lane = threadIdx.x & 31;
    int g    = lane >> 3;   // edge group 0..3 within warp
    int l8   = lane & 7;    // lane within 8-lane edge group
    int warpId = (blockIdx.x * blockDim.x + threadIdx.x) >> 5;
    long long e = (long long)warpId * 4 + g;
    bool valid = (e < E);
    int ei = valid ? (int)e : 0;

    float c = fmaxf(__ldg(curv), 1e-6f);
    float sc = sqrtf(c);

    int s = __ldg(sub + ei);
    int r = __ldg(rel + ei);
    int o = __ldg(obj + ei);
    int q = __ldg(qr + ei);

    const float* nbase = d_nodeT + (size_t)s * NODE_STRIDE;
    const float4* rrow = (const float4*)(d_relT + (size_t)r * 192);
    const float4* qrow = (const float4*)(d_relT + (size_t)q * 192);
    const float4* w4   = (const float4*)walpha_w;

    float4 x0 = ((const float4*)nbase)[l8];        // expmap0(hs) dims 4*l8..
    float4 x1 = ((const float4*)nbase)[8 + l8];    // dims 32+4*l8..
    uint4 araw = ((const uint4*)(nbase + 64))[l8]; // A cols {4l8.., 32+4l8..}
    float4 y0 = rrow[l8],      y1 = rrow[8 + l8];  // expmap0(hr)
    float4 b0 = rrow[16 + l8], b1 = rrow[24 + l8]; // hr @ Wr
    float4 c0 = qrow[32 + l8], c1 = qrow[40 + l8]; // h_qr @ Wqr + bias
    float4 w0 = w4[l8],        w1 = w4[8 + l8];

    // unpack fp16 A: first uint2 = cols 4l8..4l8+3, second = 32+4l8..
    __half2* ah = (__half2*)&araw;
    float2 a01 = __half22float2(ah[0]);   // cols 4l8, 4l8+1
    float2 a23 = __half22float2(ah[1]);   // cols 4l8+2, 4l8+3
    float2 a45 = __half22float2(ah[2]);   // cols 32+4l8, 32+4l8+1
    float2 a67 = __half22float2(ah[3]);   // cols 32+4l8+2, 32+4l8+3

    // partial dot products (8 dims per lane)
    float x2 = x0.x*x0.x + x0.y*x0.y + x0.z*x0.z + x0.w*x0.w
             + x1.x*x1.x + x1.y*x1.y + x1.z*x1.z + x1.w*x1.w;
    float y2 = y0.x*y0.x + y0.y*y0.y + y0.z*y0.z + y0.w*y0.w
             + y1.x*y1.x + y1.y*y1.y + y1.z*y1.z + y1.w*y1.w;
    float xy = x0.x*y0.x + x0.y*y0.y + x0.z*y0.z + x0.w*y0.w
             + x1.x*y1.x + x1.y*y1.y + x1.z*y1.z + x1.w*y1.w;
    float ap = fmaxf(a01.x + b0.x + c0.x, 0.f) * w0.x
             + fmaxf(a01.y + b0.y + c0.y, 0.f) * w0.y
             + fmaxf(a23.x + b0.z + c0.z, 0.f) * w0.z
             + fmaxf(a23.y + b0.w + c0.w, 0.f) * w0.w
             + fmaxf(a45.x + b1.x + c1.x, 0.f) * w1.x
             + fmaxf(a45.y + b1.y + c1.y, 0.f) * w1.y
             + fmaxf(a67.x + b1.z + c1.z, 0.f) * w1.z
             + fmaxf(a67.y + b1.w + c1.w, 0.f) * w1.w;

    // reduce within the 8-lane group
#pragma unroll
    for (int off = 4; off; off >>= 1) {
        x2 += __shfl_xor_sync(~0u, x2, off);
        y2 += __shfl_xor_sync(~0u, y2, off);
        xy += __shfl_xor_sync(~0u, xy, off);
        ap += __shfl_xor_sync(~0u, ap, off);
    }

    // mobius_add coefficients; |m|^2 from reduced scalars
    float ca = 1.f + 2.f * c * xy + c * y2;
    float cb = 1.f - c * x2;
    float den = fmaxf(1.f + 2.f * c * xy + c * c * x2 * y2, 1e-15f);
    float inv_den = 1.f / den;
    float m2 = ca * ca * x2 + 2.f * ca * cb * xy + cb * cb * y2;
    float mn = sqrtf(m2) * inv_den;

    // project + logmap0 folded into one scalar coefficient
    float maxn = 0.996f / sc;
    float pscale = 1.f, nrm = mn;
    if (mn > maxn) { pscale = maxn / mn; nrm = maxn; }
    float yn = fmaxf(nrm, 1e-15f);
    float u = fminf(sc * yn, 1.f - 1e-5f);
    float art = 0.5f * __logf((1.f + u) / (1.f - u));   // artanh
    float lf = art / (yn * sc);

    float alpha = 1.f / (1.f + __expf(-(ap + __ldg(walpha_b))));
    float coef = alpha * pscale * lf * inv_den;
    float va = ca * coef, vb = cb * coef;

    if (valid) {
        float* dst = d_agg + (size_t)o * 64 + 4 * l8;
        float p0 = va * x0.x + vb * y0.x;
        float p1 = va * x0.y + vb * y0.y;
        float p2 = va * x0.z + vb * y0.z;
        float p3 = va * x0.w + vb * y0.w;
        asm volatile("red.global.add.v4.f32 [%0], {%1, %2, %3, %4};"
                     :: "l"(dst), "f"(p0), "f"(p1), "f"(p2), "f"(p3) : "memory");
        float q0 = va * x1.x + vb * y1.x;
        float q1 = va * x1.y + vb * y1.y;
        float q2 = va * x1.z + vb * y1.z;
        float q3 = va * x1.w + vb * y1.w;
        asm volatile("red.global.add.v4.f32 [%0], {%1, %2, %3, %4};"
                     :: "l"(dst + 32), "f"(q0), "f"(q1), "f"(q2), "f"(q3) : "memory");
    }
}

// ---------------------------------------------------------------------------
// K4: out = agg @ Wh. f32x2 register-tiled matvec.
// ---------------------------------------------------------------------------
__global__ void out_gemm(const float* __restrict__ Wh, float* __restrict__ out, int nNode) {
    __shared__ float sh[16][64];
    int t = threadIdx.x;
    int base = blockIdx.x * 16;
#pragma unroll
    for (int k = 0; k < 16; k++) {
        int n = base + k;
        sh[k][t] = (n < nNode) ? d_agg[(size_t)n * 64 + t] : 0.f;
    }
    __syncthreads();

    int c4 = (t & 15) * 4;
    int ng = (t >> 4) * 4;

    unsigned long long accA[4], accB[4];
#pragma unroll
    for (int j = 0; j < 4; j++) { accA[j] = pk2(0.f, 0.f); accB[j] = pk2(0.f, 0.f); }

    for (int ib = 0; ib < 64; ib += 4) {
        float4 w0 = *(const float4*)&Wh[(size_t)(ib + 0) * 64 + c4];
        float4 w1 = *(const float4*)&Wh[(size_t)(ib + 1) * 64 + c4];
        float4 w2 = *(const float4*)&Wh[(size_t)(ib + 2) * 64 + c4];
        float4 w3 = *(const float4*)&Wh[(size_t)(ib + 3) * 64 + c4];
        unsigned long long wA0 = pk2(w0.x, w0.y), wB0 = pk2(w0.z, w0.w);
        unsigned long long wA1 = pk2(w1.x, w1.y), wB1 = pk2(w1.z, w1.w);
        unsigned long long wA2 = pk2(w2.x, w2.y), wB2 = pk2(w2.z, w2.w);
        unsigned long long wA3 = pk2(w3.x, w3.y), wB3 = pk2(w3.z, w3.w);
#pragma unroll
        for (int j = 0; j < 4; j++) {
            float4 hv = *(const float4*)&sh[ng + j][ib];
            unsigned long long h0 = pk2(hv.x, hv.x);
            unsigned long long h1 = pk2(hv.y, hv.y);
            unsigned long long h2 = pk2(hv.z, hv.z);
            unsigned long long h3 = pk2(hv.w, hv.w);
            accA[j] = fma2(h0, wA0, accA[j]); accB[j] = fma2(h0, wB0, accB[j]);
            accA[j] = fma2(h1, wA1, accA[j]); accB[j] = fma2(h1, wB1, accB[j]);
            accA[j] = fma2(h2, wA2, accA[j]); accB[j] = fma2(h2, wB2, accB[j]);
            accA[j] = fma2(h3, wA3, accA[j]); accB[j] = fma2(h3, wB3, accB[j]);
        }
    }
#pragma unroll
    for (int j = 0; j < 4; j++) {
        int n = base + ng + j;
        if (n < nNode) {
            float4 o;
            upk2(accA[j], o.x, o.y);
            upk2(accB[j], o.z, o.w);
            *(float4*)&out[(size_t)n * 64 + c4] = o;
        }
    }
}

// ---------------------------------------------------------------------------
extern "C" void kernel_launch(void* const* d_in, const int* in_sizes, int n_in,
                              void* d_out, int out_size) {
    const float* hidden   = (const float*)d_in[0];
    const float* rela     = (const float*)d_in[1];
    const float* Ws       = (const float*)d_in[2];
    const float* Wr       = (const float*)d_in[3];
    const float* Wqr      = (const float*)d_in[4];
    const float* Wqr_b    = (const float*)d_in[5];
    const float* walpha_w = (const float*)d_in[6];
    const float* walpha_b = (const float*)d_in[7];
    const float* Wh       = (const float*)d_in[8];
    const float* curv     = (const float*)d_in[9];
    const int* sub = (const int*)d_in[10];
    const int* rel = (const int*)d_in[11];
    const int* obj = (const int*)d_in[12];
    const int* qr  = (const int*)d_in[13];
    float* out = (float*)d_out;

    int nNode = in_sizes[0] / DIM;
    int nRel  = in_sizes[1] / DIM;
    int E     = in_sizes[10];

    build_rel<<<(nRel + 7) / 8, 256>>>(rela, Wr, Wqr, Wqr_b, curv, nRel);
    build_node<<<(nNode + 15) / 16, 64>>>(hidden, Ws, curv, nNode);
    int blocks = (E + 31) / 32;   // 4 edges/warp, 8 warps/block
    edge_kernel<<<blocks, 256>>>(sub, rel, obj, qr, walpha_w, walpha_b, curv, E);
    out_gemm<<<(nNode + 15) / 16, 64>>>(Wh, out, nNode);
}